// round 8
// baseline (speedup 1.0000x reference)
#include <cuda_runtime.h>

// Problem constants (fixed shapes from reference)
#define BQ    16
#define KMAX  4096
#define DKD   512
#define AA    512
#define DV    512
#define MTOT  (BQ * KMAX)      // 65536 rows
#define EPSC  1e-10f

typedef unsigned long long ull;

// -------- scratch (device globals; no allocation allowed) --------
__device__ float g_p[MTOT];        // p_choose
__device__ float g_l1[MTOT];       // log(clip(1-p))
__device__ float g_aw[MTOT];       // attention weights
__device__ float g_q[BQ * AA];     // query projection
__device__ float g_vw[AA];         // weight-normed v

// -------- packed f32x2 helpers (Blackwell FFMA2) --------
__device__ __forceinline__ ull pack2(float lo, float hi) {
    ull r; asm("mov.b64 %0, {%1,%2};" : "=l"(r) : "f"(lo), "f"(hi)); return r;
}
__device__ __forceinline__ void unpack2(float& lo, float& hi, ull v) {
    asm("mov.b64 {%0,%1}, %2;" : "=f"(lo), "=f"(hi) : "l"(v));
}
__device__ __forceinline__ void ffma2(ull& d, ull a, ull b) {
    asm("fma.rn.f32x2 %0, %1, %2, %0;" : "+l"(d) : "l"(a), "l"(b));
}

// ============================================================
// Kernel 0: v_w = v_g * v_v / ||v_v||
// ============================================================
__global__ void k_vw(const float* __restrict__ vv, const float* __restrict__ vg) {
    __shared__ float red[16];
    int t = threadIdx.x;          // 512 threads
    float v = vv[t];
    float s = v * v;
    #pragma unroll
    for (int o = 16; o; o >>= 1) s += __shfl_xor_sync(~0u, s, o);
    if ((t & 31) == 0) red[t >> 5] = s;
    __syncthreads();
    if (t < 32) {
        float x = (t < 16) ? red[t] : 0.f;
        #pragma unroll
        for (int o = 8; o; o >>= 1) x += __shfl_xor_sync(~0u, x, o);
        if (t == 0) red[0] = x;
    }
    __syncthreads();
    float inv_norm = rsqrtf(red[0]);
    g_vw[t] = vg[0] * v * inv_norm;
}

// ============================================================
// Kernel 1: q_proj[b][a] = query[b,:] . wq_w[a,:]
// grid (BQ, 64), block 256 (8 warps, one (b,a) per warp)
// ============================================================
__global__ void k_q(const float* __restrict__ query, const float* __restrict__ wq) {
    int b = blockIdx.x;
    int warp = threadIdx.x >> 5, lane = threadIdx.x & 31;
    int a = blockIdx.y * 8 + warp;
    const float* qr = query + (size_t)b * DKD;
    const float* wr = wq + (size_t)a * DKD;
    float s = 0.f;
    for (int d = lane; d < DKD; d += 32) s += qr[d] * wr[d];
    #pragma unroll
    for (int o = 16; o; o >>= 1) s += __shfl_xor_sync(~0u, s, o);
    if (lane == 0) g_q[b * AA + a] = s;
}

// ============================================================
// Kernel 2: main fused GEMM + tanh + v_w-dot + sigmoid/log
// M-tile 128 (one batch per block), N-tile 64 (x8), K-tile 32
// 256 threads, 8x4 microtile held as f32x2 pairs over M.
// ============================================================
__global__ __launch_bounds__(256, 2)
void k_main(const float* __restrict__ key, const float* __restrict__ wk,
            const float* __restrict__ wkb, const float* __restrict__ noise,
            const float* __restrict__ rr)
{
    __shared__ float As[32][132];   // [k][m], padded, rows 16B-aligned
    __shared__ float Bs[32][68];    // [k][n], padded, rows 16B-aligned

    const int tid = threadIdx.x;
    const int tx = tid & 15;        // n-group
    const int ty = tid >> 4;        // m-group
    const int m0 = blockIdx.x * 128;
    const int b  = m0 >> 12;        // 4096 rows per batch, 128 | 4096
    const int lrow = tid >> 3;          // 0..31  (load row within pass)
    const int lcol = (tid & 7) << 2;    // 0..28  (float4 column)

    float ep[8];
    #pragma unroll
    for (int i = 0; i < 8; i++) ep[i] = 0.f;

    for (int n0 = 0; n0 < AA; n0 += 64) {
        ull acc[4][4];
        #pragma unroll
        for (int mp = 0; mp < 4; mp++)
            #pragma unroll
            for (int j = 0; j < 4; j++) acc[mp][j] = 0ull;

        for (int kk = 0; kk < DKD; kk += 32) {
            // load key tile 128x32 -> As transposed
            #pragma unroll
            for (int pa = 0; pa < 4; pa++) {
                int r = lrow + pa * 32;
                const float4 v = *reinterpret_cast<const float4*>(
                    key + (size_t)(m0 + r) * DKD + kk + lcol);
                As[lcol + 0][r] = v.x;
                As[lcol + 1][r] = v.y;
                As[lcol + 2][r] = v.z;
                As[lcol + 3][r] = v.w;
            }
            // load wk tile 64x32 -> Bs transposed
            #pragma unroll
            for (int pb = 0; pb < 2; pb++) {
                int r = lrow + pb * 32;
                const float4 v = *reinterpret_cast<const float4*>(
                    wk + (size_t)(n0 + r) * DKD + kk + lcol);
                Bs[lcol + 0][r] = v.x;
                Bs[lcol + 1][r] = v.y;
                Bs[lcol + 2][r] = v.z;
                Bs[lcol + 3][r] = v.w;
            }
            __syncthreads();

            #pragma unroll
            for (int k = 0; k < 32; k++) {
                const float4 a0 = *reinterpret_cast<const float4*>(&As[k][ty * 8]);
                const float4 a1 = *reinterpret_cast<const float4*>(&As[k][ty * 8 + 4]);
                const float4 bv = *reinterpret_cast<const float4*>(&Bs[k][tx * 4]);
                ull ap[4];
                ap[0] = pack2(a0.x, a0.y);
                ap[1] = pack2(a0.z, a0.w);
                ap[2] = pack2(a1.x, a1.y);
                ap[3] = pack2(a1.z, a1.w);
                ull bb[4];
                bb[0] = pack2(bv.x, bv.x);
                bb[1] = pack2(bv.y, bv.y);
                bb[2] = pack2(bv.z, bv.z);
                bb[3] = pack2(bv.w, bv.w);
                #pragma unroll
                for (int mp = 0; mp < 4; mp++)
                    #pragma unroll
                    for (int j = 0; j < 4; j++)
                        ffma2(acc[mp][j], ap[mp], bb[j]);
            }
            __syncthreads();
        }

        // epilogue for this n-chunk: tanh(c + bias + q) * v_w, accumulate over n
        const int ng = n0 + tx * 4;
        const float4 bias = *reinterpret_cast<const float4*>(wkb + ng);
        const float4 qv   = *reinterpret_cast<const float4*>(g_q + b * AA + ng);
        const float4 vw4  = *reinterpret_cast<const float4*>(g_vw + ng);
        float bj[4] = {bias.x + qv.x, bias.y + qv.y, bias.z + qv.z, bias.w + qv.w};
        float vj[4] = {vw4.x, vw4.y, vw4.z, vw4.w};

        #pragma unroll
        for (int mp = 0; mp < 4; mp++) {
            #pragma unroll
            for (int j = 0; j < 4; j++) {
                float lo, hi;
                unpack2(lo, hi, acc[mp][j]);
                ep[mp * 2 + 0] += tanhf(lo + bj[j]) * vj[j];
                ep[mp * 2 + 1] += tanhf(hi + bj[j]) * vj[j];
            }
        }
    }

    // reduce the 16 n-lanes (tx = low 4 lane bits within each warp)
    #pragma unroll
    for (int i = 0; i < 8; i++) {
        float v = ep[i];
        v += __shfl_xor_sync(~0u, v, 1);
        v += __shfl_xor_sync(~0u, v, 2);
        v += __shfl_xor_sync(~0u, v, 4);
        v += __shfl_xor_sync(~0u, v, 8);
        ep[i] = v;
    }

    if (tx == 0) {
        const float rv = rr[0];
        #pragma unroll
        for (int i = 0; i < 8; i++) {
            int m = m0 + ty * 8 + i;
            float e = ep[i] + rv + noise[m];
            float pp = 1.f / (1.f + expf(-e));
            g_p[m] = pp;
            float om = fminf(fmaxf(1.f - pp, EPSC), 1.f);
            g_l1[m] = logf(om);
        }
    }
}

// ============================================================
// Kernel 3: per-batch scan.
// aw_prev one-hot(0) & clip(cp[0]=e^1)=1  =>  aw[k] = p[k]*exp(1+sum_{i<k} l1[i])
// grid BQ, 256 threads x 16 elems. Also zeros the cv output region.
// ============================================================
__global__ void k_scan(float* __restrict__ out) {
    __shared__ float ws[256];
    const int b = blockIdx.x, t = threadIdx.x;
    const float* l1 = g_l1 + b * KMAX;
    const float* p  = g_p  + b * KMAX;

    float loc[16];
    float s = 0.f;
    const int base = t * 16;
    #pragma unroll
    for (int i = 0; i < 16; i++) {
        int idx = base + i;
        float x = (idx == 0) ? 1.0f : l1[idx - 1];
        s += x;
        loc[i] = s;              // inclusive within thread
    }
    ws[t] = s;
    __syncthreads();
    for (int off = 1; off < 256; off <<= 1) {
        float v = (t >= off) ? ws[t - off] : 0.f;
        __syncthreads();
        ws[t] += v;
        __syncthreads();
    }
    float pre = (t == 0) ? 0.f : ws[t - 1];

    float* aw = g_aw + b * KMAX;
    #pragma unroll
    for (int i = 0; i < 16; i++) {
        int idx = base + i;
        aw[idx] = p[idx] * expf(pre + loc[i]);
    }
    // zero cv region of output (atomically accumulated by k_cv)
    out[b * DV + t] = 0.f;
    out[b * DV + 256 + t] = 0.f;
}

// ============================================================
// Kernel 4: cv[b][v] = sum_k aw[b,k] * value[b,k,v]
// grid (BQ, 16) k-slices of 256; block 512 threads (v)
// ============================================================
__global__ void k_cv(const float* __restrict__ value, float* __restrict__ out) {
    const int b = blockIdx.x, ks = blockIdx.y;
    const int v = threadIdx.x;
    const float* aw = g_aw + b * KMAX + ks * 256;
    const float* val = value + ((size_t)b * KMAX + (size_t)ks * 256) * DV + v;
    float acc = 0.f;
    #pragma unroll 4
    for (int k = 0; k < 256; k++) acc += aw[k] * val[(size_t)k * DV];
    atomicAdd(&out[b * DV + v], acc);
}

// ============================================================
// Kernel 5: copy aw into the output buffer (after cv region)
// ============================================================
__global__ void k_aw_out(float* __restrict__ out) {
    int i = blockIdx.x * 256 + threadIdx.x;
    out[BQ * DV + i] = g_aw[i];
}

extern "C" void kernel_launch(void* const* d_in, const int* in_sizes, int n_in,
                              void* d_out, int out_size) {
    const float* key   = (const float*)d_in[0];  // [B,KMAX,DK]
    const float* value = (const float*)d_in[1];  // [B,KMAX,DV]
    const float* query = (const float*)d_in[2];  // [B,1,DQ]
    const float* noise = (const float*)d_in[3];  // [B,KMAX]
    const float* wkw   = (const float*)d_in[4];  // [A,DK]
    const float* wkb   = (const float*)d_in[5];  // [A]
    const float* wqw   = (const float*)d_in[6];  // [A,DQ]
    const float* vv    = (const float*)d_in[7];  // [1,A]
    const float* vg    = (const float*)d_in[8];  // [1]
    const float* r     = (const float*)d_in[9];  // [1]
    float* out = (float*)d_out;                  // cv [B,1,DV] then aw [B,KMAX,1]

    k_vw<<<1, 512>>>(vv, vg);
    k_q<<<dim3(BQ, 64), 256>>>(query, wqw);
    k_main<<<MTOT / 128, 256>>>(key, wkw, wkb, noise, r);
    k_scan<<<BQ, 256>>>(out);
    k_cv<<<dim3(BQ, 16), 512>>>(value, out);
    if (out_size >= BQ * DV + MTOT) {
        k_aw_out<<<MTOT / 256, 256>>>(out);
    }
}

// round 10
// speedup vs baseline: 4.3988x; 4.3988x over previous
#include <cuda_runtime.h>
#include <cstdint>

// Problem constants (fixed shapes from reference)
#define BQ    16
#define KMAX  4096
#define DKD   512
#define AA    512
#define DV    512
#define MTOT  (BQ * KMAX)      // 65536 rows
#define EPSC  1e-10f

// -------- scratch (device globals; no allocation allowed) --------
__device__ float g_p[MTOT];        // p_choose
__device__ float g_l1[MTOT];       // log(clip(1-p))
__device__ float g_aw[MTOT];       // attention weights
__device__ float g_q[BQ * AA];     // query projection
__device__ float g_vw[AA];         // weight-normed v

// ============================================================
// helpers (family-generic PTX only: sm_80-era)
// ============================================================
__device__ __forceinline__ uint32_t smem_u32(const void* p) {
    uint32_t a;
    asm("{ .reg .u64 t; cvta.to.shared.u64 t, %1; cvt.u32.u64 %0, t; }"
        : "=r"(a) : "l"(p));
    return a;
}
__device__ __forceinline__ float tanh_ap(float x) {
    float y; asm("tanh.approx.f32 %0, %1;" : "=f"(y) : "f"(x)); return y;
}
__device__ __forceinline__ void cp16(uint32_t dst, const void* src) {
    asm volatile("cp.async.cg.shared.global [%0], [%1], 16;"
                 :: "r"(dst), "l"(src) : "memory");
}
__device__ __forceinline__ void cp_commit() {
    asm volatile("cp.async.commit_group;" ::: "memory");
}
template <int N> __device__ __forceinline__ void cp_wait() {
    asm volatile("cp.async.wait_group %0;" :: "n"(N) : "memory");
}
// m16n8k8 tf32 MMA (sm_80+; fp32 bits fed directly -> HW truncates to tf32)
__device__ __forceinline__ void mma8(float* c, const uint32_t* a, const uint32_t* b) {
    asm volatile(
        "mma.sync.aligned.m16n8k8.row.col.f32.tf32.tf32.f32 "
        "{%0,%1,%2,%3}, {%4,%5,%6,%7}, {%8,%9}, {%0,%1,%2,%3};"
        : "+f"(c[0]), "+f"(c[1]), "+f"(c[2]), "+f"(c[3])
        : "r"(a[0]), "r"(a[1]), "r"(a[2]), "r"(a[3]), "r"(b[0]), "r"(b[1]));
}

// ============================================================
// Kernel 0: v_w = v_g * v_v / ||v_v||
// ============================================================
__global__ void k_vw(const float* __restrict__ vv, const float* __restrict__ vg) {
    __shared__ float red[16];
    int t = threadIdx.x;          // 512 threads
    float v = vv[t];
    float s = v * v;
    #pragma unroll
    for (int o = 16; o; o >>= 1) s += __shfl_xor_sync(~0u, s, o);
    if ((t & 31) == 0) red[t >> 5] = s;
    __syncthreads();
    if (t < 32) {
        float x = (t < 16) ? red[t] : 0.f;
        #pragma unroll
        for (int o = 8; o; o >>= 1) x += __shfl_xor_sync(~0u, x, o);
        if (t == 0) red[0] = x;
    }
    __syncthreads();
    float inv_norm = rsqrtf(red[0]);
    g_vw[t] = vg[0] * v * inv_norm;
}

// ============================================================
// Kernel 1: q_proj[b][a] = query[b,:] . wq_w[a,:]
// ============================================================
__global__ void k_q(const float* __restrict__ query, const float* __restrict__ wq) {
    int b = blockIdx.x;
    int warp = threadIdx.x >> 5, lane = threadIdx.x & 31;
    int a = blockIdx.y * 8 + warp;
    const float* qr = query + (size_t)b * DKD;
    const float* wr = wq + (size_t)a * DKD;
    float s = 0.f;
    for (int d = lane; d < DKD; d += 32) s += qr[d] * wr[d];
    #pragma unroll
    for (int o = 16; o; o >>= 1) s += __shfl_xor_sync(~0u, s, o);
    if (lane == 0) g_q[b * AA + a] = s;
}

// ============================================================
// Kernel 2: tf32 mma.sync GEMM + fused tanh/vw/sigmoid epilogue
//   CTA: 128 M-rows. 8 N-chunks of 64. K-chunks of 32, 2-stage
//   cp.async double buffer. 8 warps: 4 along M x 2 along N,
//   warp tile 32x32 = 2 (m16) x 4 (n8) mma tiles.
// ============================================================
#define LDA 36                         // floats per SMEM row (144B, 16B aligned)
#define A_ST_FLT (128 * LDA)           // 4608
#define B_ST_FLT (64 * LDA)            // 2304
#define STG_FLT  (A_ST_FLT + B_ST_FLT) // 6912 floats = 27648 B
#define CB_OFF   (2 * STG_FLT)         // 13824
#define VS_OFF   (CB_OFF + 512)
#define RED_OFF  (VS_OFF + 512)
#define SMEM_FLT (RED_OFF + 128)       // 14976 floats
#define SMEM_BYTES (SMEM_FLT * 4)      // 59904

__global__ __launch_bounds__(256, 3)
void k_main(const float* __restrict__ key, const float* __restrict__ wk,
            const float* __restrict__ wkb, const float* __restrict__ noise,
            const float* __restrict__ rr)
{
    extern __shared__ float sm[];
    float* cb  = sm + CB_OFF;
    float* vs  = sm + VS_OFF;
    float* red = sm + RED_OFF;

    const int tid  = threadIdx.x;
    const int lane = tid & 31;
    const int wid  = tid >> 5;
    const int wm   = wid >> 1;        // 0..3 (M)
    const int wn   = wid & 1;         // 0..1 (N)
    const int g    = lane >> 2;       // group 0..7
    const int t4   = lane & 3;
    const int m0   = blockIdx.x * 128;
    const int b    = blockIdx.x >> 5; // 32 M-tiles per batch

    // preload epilogue coefficients
    for (int i = tid; i < 512; i += 256) {
        cb[i] = wkb[i] + g_q[b * AA + i];
        vs[i] = g_vw[i];
    }
    __syncthreads();

    const uint32_t sbase = smem_u32(sm);
    float ep[4] = {0.f, 0.f, 0.f, 0.f};

    // per-thread cp.async decomposition (A: 4 xfer, B: 2 xfer per chunk)
    const int lr = tid >> 3;          // 0..31
    const int lc4 = tid & 7;          // 0..7

    for (int n0 = 0; n0 < AA; n0 += 64) {
        float C[2][4][4];
        #pragma unroll
        for (int im = 0; im < 2; im++)
            #pragma unroll
            for (int jn = 0; jn < 4; jn++)
                #pragma unroll
                for (int r = 0; r < 4; r++) C[im][jn][r] = 0.f;

        // ---- pipeline issue for chunk c into stage c&1 ----
        auto issue = [&](int c) {
            const int kk = c * 32;
            const uint32_t bA = sbase + (c & 1) * (STG_FLT * 4);
            const uint32_t bB = bA + A_ST_FLT * 4;
            const float* Ag = key + (size_t)(m0 + lr) * DKD + kk + lc4 * 4;
            #pragma unroll
            for (int it = 0; it < 4; ++it)
                cp16(bA + (lr + it * 32) * (LDA * 4) + lc4 * 16,
                     Ag + (size_t)(it * 32) * DKD);
            const float* Bg = wk + (size_t)(n0 + lr) * DKD + kk + lc4 * 4;
            #pragma unroll
            for (int it = 0; it < 2; ++it)
                cp16(bB + (lr + it * 32) * (LDA * 4) + lc4 * 16,
                     Bg + (size_t)(it * 32) * DKD);
            cp_commit();
        };

        issue(0);
        for (int c = 0; c < 16; ++c) {
            if (c + 1 < 16) issue(c + 1);
            if (c + 1 < 16) cp_wait<1>(); else cp_wait<0>();
            __syncthreads();

            const float* As = sm + (c & 1) * STG_FLT;
            const float* Bs = As + A_ST_FLT;

            #pragma unroll
            for (int ks = 0; ks < 4; ++ks) {
                const int kc = ks * 8 + t4;
                uint32_t afr[2][4], bfr[4][2];
                #pragma unroll
                for (int im = 0; im < 2; ++im) {
                    const int r = wm * 32 + im * 16 + g;
                    afr[im][0] = __float_as_uint(As[r * LDA + kc]);
                    afr[im][1] = __float_as_uint(As[(r + 8) * LDA + kc]);
                    afr[im][2] = __float_as_uint(As[r * LDA + kc + 4]);
                    afr[im][3] = __float_as_uint(As[(r + 8) * LDA + kc + 4]);
                }
                #pragma unroll
                for (int jn = 0; jn < 4; ++jn) {
                    const int n = wn * 32 + jn * 8 + g;
                    bfr[jn][0] = __float_as_uint(Bs[n * LDA + kc]);
                    bfr[jn][1] = __float_as_uint(Bs[n * LDA + kc + 4]);
                }
                #pragma unroll
                for (int im = 0; im < 2; ++im)
                    #pragma unroll
                    for (int jn = 0; jn < 4; ++jn)
                        mma8(C[im][jn], afr[im], bfr[jn]);
            }
            __syncthreads();
        }

        // ---- epilogue for this n-chunk: tanh(C + cb) . vs ----
        #pragma unroll
        for (int im = 0; im < 2; ++im)
            #pragma unroll
            for (int jn = 0; jn < 4; ++jn)
                #pragma unroll
                for (int r = 0; r < 4; ++r) {
                    const int col = n0 + wn * 32 + jn * 8 + t4 * 2 + (r & 1);
                    const float x = C[im][jn][r] + cb[col];
                    ep[im * 2 + (r >> 1)] += tanh_ap(x) * vs[col];
                }
    }

    // reduce over the 4 lanes sharing rows (t4), then combine the 2 N-warps
    #pragma unroll
    for (int i = 0; i < 4; ++i) {
        ep[i] += __shfl_xor_sync(~0u, ep[i], 1);
        ep[i] += __shfl_xor_sync(~0u, ep[i], 2);
    }
    if (t4 == 0 && wn == 0) {
        #pragma unroll
        for (int i = 0; i < 4; ++i)
            red[wm * 32 + (i >> 1) * 16 + (i & 1) * 8 + g] = ep[i];
    }
    __syncthreads();
    if (t4 == 0 && wn == 1) {
        #pragma unroll
        for (int i = 0; i < 4; ++i)
            red[wm * 32 + (i >> 1) * 16 + (i & 1) * 8 + g] += ep[i];
    }
    __syncthreads();

    if (tid < 128) {
        const int m = m0 + tid;
        const float e = red[tid] + rr[0] + noise[m];
        const float pp = 1.f / (1.f + expf(-e));
        g_p[m] = pp;
        g_l1[m] = logf(fminf(fmaxf(1.f - pp, EPSC), 1.f));
    }
}

// ============================================================
// Kernel 3: per-batch scan + aw output + zero cv region
//   aw[k] = p[k] * exp(1 + sum_{i<k} l1[i])
// ============================================================
__global__ void k_scan(float* __restrict__ out) {
    __shared__ float ws[512];
    const int b = blockIdx.x, t = threadIdx.x;     // 512 threads x 8 elems
    const float* l1 = g_l1 + b * KMAX;
    const float* p  = g_p  + b * KMAX;

    float loc[8];
    float s = 0.f;
    const int base = t * 8;
    #pragma unroll
    for (int i = 0; i < 8; i++) {
        int idx = base + i;
        float x = (idx == 0) ? 1.0f : l1[idx - 1];
        s += x;
        loc[i] = s;              // inclusive within thread
    }
    ws[t] = s;
    __syncthreads();
    for (int off = 1; off < 512; off <<= 1) {
        float v = (t >= off) ? ws[t - off] : 0.f;
        __syncthreads();
        ws[t] += v;
        __syncthreads();
    }
    float pre = (t == 0) ? 0.f : ws[t - 1];

    float* aw = g_aw + b * KMAX;
    float* awo = out + BQ * DV + b * KMAX;
    #pragma unroll
    for (int i = 0; i < 8; i++) {
        int idx = base + i;
        float v = p[idx] * expf(pre + loc[i]);
        aw[idx] = v;
        awo[idx] = v;
    }
    out[b * DV + t] = 0.f;   // zero cv region (accumulated by k_cv)
}

// ============================================================
// Kernel 4: cv[b][v] = sum_k aw[b,k] * value[b,k,v]
// ============================================================
__global__ void k_cv(const float* __restrict__ value, float* __restrict__ out) {
    const int b = blockIdx.x, ks = blockIdx.y;
    const int v = threadIdx.x;
    const float* aw = g_aw + b * KMAX + ks * 256;
    const float* val = value + ((size_t)b * KMAX + (size_t)ks * 256) * DV + v;
    float acc = 0.f;
    #pragma unroll 4
    for (int k = 0; k < 256; k++) acc += aw[k] * val[(size_t)k * DV];
    atomicAdd(&out[b * DV + v], acc);
}

extern "C" void kernel_launch(void* const* d_in, const int* in_sizes, int n_in,
                              void* d_out, int out_size) {
    const float* key   = (const float*)d_in[0];  // [B,KMAX,DK]
    const float* value = (const float*)d_in[1];  // [B,KMAX,DV]
    const float* query = (const float*)d_in[2];  // [B,1,DQ]
    const float* noise = (const float*)d_in[3];  // [B,KMAX]
    const float* wkw   = (const float*)d_in[4];  // [A,DK]
    const float* wkb   = (const float*)d_in[5];  // [A]
    const float* wqw   = (const float*)d_in[6];  // [A,DQ]
    const float* vv    = (const float*)d_in[7];  // [1,A]
    const float* vg    = (const float*)d_in[8];  // [1]
    const float* r     = (const float*)d_in[9];  // [1]
    float* out = (float*)d_out;                  // cv [B,1,DV] then aw [B,KMAX,1]

    cudaFuncSetAttribute(k_main, cudaFuncAttributeMaxDynamicSharedMemorySize, SMEM_BYTES);

    k_vw<<<1, 512>>>(vv, vg);
    k_q<<<dim3(BQ, 64), 256>>>(query, wqw);
    k_main<<<MTOT / 128, 256, SMEM_BYTES>>>(key, wkw, wkb, noise, r);
    k_scan<<<BQ, 512>>>(out);
    k_cv<<<dim3(BQ, 16), 512>>>(value, out);
}

// round 11
// speedup vs baseline: 5.9674x; 1.3566x over previous
#include <cuda_runtime.h>
#include <cstdint>

// Problem constants (fixed shapes from reference)
#define BQ    16
#define KMAX  4096
#define DKD   512
#define AA    512
#define DV    512
#define MTOT  (BQ * KMAX)      // 65536 rows
#define EPSC  1e-10f

// -------- scratch (device globals; no allocation allowed) --------
__device__ float g_p[MTOT];        // p_choose
__device__ float g_l1[MTOT];       // log(clip(1-p))
__device__ float g_aw[MTOT];       // attention weights
__device__ float g_q[BQ * AA];     // query projection
__device__ float g_vw[AA];         // weight-normed v

// ============================================================
// helpers (family-generic PTX only: sm_80-era)
// ============================================================
__device__ __forceinline__ uint32_t smem_u32(const void* p) {
    uint32_t a;
    asm("{ .reg .u64 t; cvta.to.shared.u64 t, %1; cvt.u32.u64 %0, t; }"
        : "=r"(a) : "l"(p));
    return a;
}
__device__ __forceinline__ float tanh_ap(float x) {
    float y; asm("tanh.approx.f32 %0, %1;" : "=f"(y) : "f"(x)); return y;
}
__device__ __forceinline__ void cp16(uint32_t dst, const void* src) {
    asm volatile("cp.async.cg.shared.global [%0], [%1], 16;"
                 :: "r"(dst), "l"(src) : "memory");
}
__device__ __forceinline__ void cp_commit() {
    asm volatile("cp.async.commit_group;" ::: "memory");
}
template <int N> __device__ __forceinline__ void cp_wait() {
    asm volatile("cp.async.wait_group %0;" :: "n"(N) : "memory");
}
// m16n8k8 tf32 MMA (sm_80+; fp32 bits fed directly -> HW truncates to tf32)
__device__ __forceinline__ void mma8(float* c, const uint32_t* a, const uint32_t* b) {
    asm volatile(
        "mma.sync.aligned.m16n8k8.row.col.f32.tf32.tf32.f32 "
        "{%0,%1,%2,%3}, {%4,%5,%6,%7}, {%8,%9}, {%0,%1,%2,%3};"
        : "+f"(c[0]), "+f"(c[1]), "+f"(c[2]), "+f"(c[3])
        : "r"(a[0]), "r"(a[1]), "r"(a[2]), "r"(a[3]), "r"(b[0]), "r"(b[1]));
}

// ============================================================
// Kernel 0: v_w = v_g * v_v / ||v_v||
// ============================================================
__global__ void k_vw(const float* __restrict__ vv, const float* __restrict__ vg) {
    __shared__ float red[16];
    int t = threadIdx.x;          // 512 threads
    float v = vv[t];
    float s = v * v;
    #pragma unroll
    for (int o = 16; o; o >>= 1) s += __shfl_xor_sync(~0u, s, o);
    if ((t & 31) == 0) red[t >> 5] = s;
    __syncthreads();
    if (t < 32) {
        float x = (t < 16) ? red[t] : 0.f;
        #pragma unroll
        for (int o = 8; o; o >>= 1) x += __shfl_xor_sync(~0u, x, o);
        if (t == 0) red[0] = x;
    }
    __syncthreads();
    float inv_norm = rsqrtf(red[0]);
    g_vw[t] = vg[0] * v * inv_norm;
}

// ============================================================
// Kernel 1: q_proj[b][a] = query[b,:] . wq_w[a,:]
// ============================================================
__global__ void k_q(const float* __restrict__ query, const float* __restrict__ wq) {
    int b = blockIdx.x;
    int warp = threadIdx.x >> 5, lane = threadIdx.x & 31;
    int a = blockIdx.y * 8 + warp;
    const float* qr = query + (size_t)b * DKD;
    const float* wr = wq + (size_t)a * DKD;
    float s = 0.f;
    for (int d = lane; d < DKD; d += 32) s += qr[d] * wr[d];
    #pragma unroll
    for (int o = 16; o; o >>= 1) s += __shfl_xor_sync(~0u, s, o);
    if (lane == 0) g_q[b * AA + a] = s;
}

// ============================================================
// Kernel 2: tf32 mma.sync GEMM + fused tanh/vw/sigmoid epilogue
//   CTA: 128 M x 128 N-chunk (x4), K-chunks of 32, 3-stage
//   cp.async pipeline (1 sync/chunk). 8 warps: 4M x 2N,
//   warp tile 32x128 = 2 (m16) x 8 (n8) mma tiles.
//   SMEM XOR-swizzled: row 32 floats, slot = col4 ^ (row&7).
// ============================================================
#define STG_FLT  8192                  // A 128x32 + B 128x32 floats
#define NSTAGE   3
#define DYN_BYTES (NSTAGE * STG_FLT * 4)   // 98304

__global__ __launch_bounds__(256, 2)
void k_main(const float* __restrict__ key, const float* __restrict__ wk,
            const float* __restrict__ wkb, const float* __restrict__ noise,
            const float* __restrict__ rr)
{
    extern __shared__ float sm[];          // 3 stages
    __shared__ float cb[512], vs[512], red[128];

    const int tid  = threadIdx.x;
    const int lane = tid & 31;
    const int wid  = tid >> 5;
    const int wm   = wid >> 1;        // 0..3 (M, 32 rows each)
    const int wn   = wid & 1;         // 0..1 (N, 64 cols each)
    const int g    = lane >> 2;       // 0..7
    const int t4   = lane & 3;        // 0..3
    const int m0   = blockIdx.x * 128;
    const int b    = blockIdx.x >> 5; // 32 M-tiles per batch

    for (int i = tid; i < 512; i += 256) {
        cb[i] = wkb[i] + g_q[b * AA + i];
        vs[i] = g_vw[i];
    }

    const uint32_t sbase = smem_u32(sm);
    const int lr  = tid >> 3;         // 0..31 (row group for cp.async)
    const int lc4 = tid & 7;          // 0..7  (float4 col)
    const int sw  = lr & 7;           // swizzle key for this thread's rows

    float ep[4] = {0.f, 0.f, 0.f, 0.f};

    for (int n0 = 0; n0 < AA; n0 += 128) {
        float C[2][8][4];
        #pragma unroll
        for (int im = 0; im < 2; im++)
            #pragma unroll
            for (int jn = 0; jn < 8; jn++)
                #pragma unroll
                for (int r = 0; r < 4; r++) C[im][jn][r] = 0.f;

        // issue chunk c into stage c%3 (A 128x32 + B 128x32, swizzled)
        auto issue = [&](int c) {
            const int kk = c * 32;
            const uint32_t st = sbase + (c % NSTAGE) * (STG_FLT * 4);
            const uint32_t dcol = (uint32_t)(lc4 ^ sw) * 16;
            const float* Ag = key + (size_t)(m0 + lr) * DKD + kk + lc4 * 4;
            #pragma unroll
            for (int it = 0; it < 4; ++it)
                cp16(st + (lr + it * 32) * 128 + dcol,
                     Ag + (size_t)(it * 32) * DKD);
            const float* Bg = wk + (size_t)(n0 + lr) * DKD + kk + lc4 * 4;
            #pragma unroll
            for (int it = 0; it < 4; ++it)
                cp16(st + 16384 + (lr + it * 32) * 128 + dcol,
                     Bg + (size_t)(it * 32) * DKD);
            cp_commit();
        };

        __syncthreads();            // stages free from previous n-chunk
        issue(0); issue(1);

        for (int c = 0; c < 16; ++c) {
            if (c < 15) cp_wait<1>(); else cp_wait<0>();
            __syncthreads();
            if (c + 2 < 16) issue(c + 2);

            const float* As = sm + (c % NSTAGE) * STG_FLT;
            const float* Bs = As + 4096;
            // per-thread fragment bases (swizzle key = g for all frag rows)
            const float* Ab = As + (wm * 32 + g) * 32 + t4;
            const float* Bb = Bs + (wn * 64 + g) * 32 + t4;

            #pragma unroll
            for (int ks = 0; ks < 4; ++ks) {
                const int s0 = ((ks << 1) ^ g) << 2;       // slot*4
                const int s1 = (((ks << 1) | 1) ^ g) << 2;
                uint32_t afr[2][4];
                #pragma unroll
                for (int im = 0; im < 2; ++im) {
                    const float* p = Ab + im * 512;        // +16 rows
                    afr[im][0] = __float_as_uint(p[s0]);
                    afr[im][1] = __float_as_uint(p[256 + s0]);  // +8 rows
                    afr[im][2] = __float_as_uint(p[s1]);
                    afr[im][3] = __float_as_uint(p[256 + s1]);
                }
                #pragma unroll
                for (int jn = 0; jn < 8; ++jn) {
                    uint32_t bfr[2];
                    bfr[0] = __float_as_uint(Bb[jn * 256 + s0]);
                    bfr[1] = __float_as_uint(Bb[jn * 256 + s1]);
                    mma8(C[0][jn], afr[0], bfr);
                    mma8(C[1][jn], afr[1], bfr);
                }
            }
        }

        // epilogue for this n-chunk: tanh(C + cb) . vs
        #pragma unroll
        for (int im = 0; im < 2; ++im)
            #pragma unroll
            for (int jn = 0; jn < 8; ++jn)
                #pragma unroll
                for (int r = 0; r < 4; ++r) {
                    const int col = n0 + wn * 64 + jn * 8 + t4 * 2 + (r & 1);
                    const float x = C[im][jn][r] + cb[col];
                    ep[im * 2 + (r >> 1)] += tanh_ap(x) * vs[col];
                }
    }

    // reduce over the 4 k-lanes (t4), then combine the 2 N-warps
    #pragma unroll
    for (int i = 0; i < 4; ++i) {
        ep[i] += __shfl_xor_sync(~0u, ep[i], 1);
        ep[i] += __shfl_xor_sync(~0u, ep[i], 2);
    }
    __syncthreads();
    if (t4 == 0 && wn == 0) {
        #pragma unroll
        for (int i = 0; i < 4; ++i)
            red[wm * 32 + (i >> 1) * 16 + (i & 1) * 8 + g] = ep[i];
    }
    __syncthreads();
    if (t4 == 0 && wn == 1) {
        #pragma unroll
        for (int i = 0; i < 4; ++i)
            red[wm * 32 + (i >> 1) * 16 + (i & 1) * 8 + g] += ep[i];
    }
    __syncthreads();

    if (tid < 128) {
        const int m = m0 + tid;
        const float e = red[tid] + rr[0] + noise[m];
        const float pp = 1.f / (1.f + expf(-e));
        g_p[m] = pp;
        g_l1[m] = logf(fminf(fmaxf(1.f - pp, EPSC), 1.f));
    }
}

// ============================================================
// Kernel 3: per-batch scan + aw output + zero cv region
//   aw[k] = p[k] * exp(1 + sum_{i<k} l1[i])
// ============================================================
__global__ void k_scan(float* __restrict__ out) {
    __shared__ float ws[512];
    const int b = blockIdx.x, t = threadIdx.x;     // 512 threads x 8 elems
    const float* l1 = g_l1 + b * KMAX;
    const float* p  = g_p  + b * KMAX;

    float loc[8];
    float s = 0.f;
    const int base = t * 8;
    #pragma unroll
    for (int i = 0; i < 8; i++) {
        int idx = base + i;
        float x = (idx == 0) ? 1.0f : l1[idx - 1];
        s += x;
        loc[i] = s;              // inclusive within thread
    }
    ws[t] = s;
    __syncthreads();
    for (int off = 1; off < 512; off <<= 1) {
        float v = (t >= off) ? ws[t - off] : 0.f;
        __syncthreads();
        ws[t] += v;
        __syncthreads();
    }
    float pre = (t == 0) ? 0.f : ws[t - 1];

    float* aw = g_aw + b * KMAX;
    float* awo = out + BQ * DV + b * KMAX;
    #pragma unroll
    for (int i = 0; i < 8; i++) {
        int idx = base + i;
        float v = p[idx] * expf(pre + loc[i]);
        aw[idx] = v;
        awo[idx] = v;
    }
    out[b * DV + t] = 0.f;   // zero cv region (accumulated by k_cv)
}

// ============================================================
// Kernel 4: cv[b][v] = sum_k aw[b,k] * value[b,k,v]
// ============================================================
__global__ void k_cv(const float* __restrict__ value, float* __restrict__ out) {
    const int b = blockIdx.x, ks = blockIdx.y;
    const int v = threadIdx.x;
    const float* aw = g_aw + b * KMAX + ks * 256;
    const float* val = value + ((size_t)b * KMAX + (size_t)ks * 256) * DV + v;
    float acc = 0.f;
    #pragma unroll 8
    for (int k = 0; k < 256; k++) acc += aw[k] * __ldg(val + (size_t)k * DV);
    atomicAdd(&out[b * DV + v], acc);
}

extern "C" void kernel_launch(void* const* d_in, const int* in_sizes, int n_in,
                              void* d_out, int out_size) {
    const float* key   = (const float*)d_in[0];  // [B,KMAX,DK]
    const float* value = (const float*)d_in[1];  // [B,KMAX,DV]
    const float* query = (const float*)d_in[2];  // [B,1,DQ]
    const float* noise = (const float*)d_in[3];  // [B,KMAX]
    const float* wkw   = (const float*)d_in[4];  // [A,DK]
    const float* wkb   = (const float*)d_in[5];  // [A]
    const float* wqw   = (const float*)d_in[6];  // [A,DQ]
    const float* vv    = (const float*)d_in[7];  // [1,A]
    const float* vg    = (const float*)d_in[8];  // [1]
    const float* r     = (const float*)d_in[9];  // [1]
    float* out = (float*)d_out;                  // cv [B,1,DV] then aw [B,KMAX,1]

    cudaFuncSetAttribute(k_main, cudaFuncAttributeMaxDynamicSharedMemorySize, DYN_BYTES);

    k_vw<<<1, 512>>>(vv, vg);
    k_q<<<dim3(BQ, 64), 256>>>(query, wqw);
    k_main<<<MTOT / 128, 256, DYN_BYTES>>>(key, wkw, wkb, noise, r);
    k_scan<<<BQ, 512>>>(out);
    k_cv<<<dim3(BQ, 16), 512>>>(value, out);
}